// round 15
// baseline (speedup 1.0000x reference)
#include <cuda_runtime.h>
#include <math.h>
#include <stdint.h>

#define B_SAMPLES 512
#define M_ROWS    24
#define D_DIM     4096
#define CHUNK     256                 // floats of K per stage (1KB per row)
#define NSTAGE    (D_DIM / CHUNK)     // 16
#define THREADS   128                 // 4 warps
#define GRID      B_SAMPLES
#define P         260                 // smem row pitch (floats): 260%32==4 bank-spread
#define STAGEF    (M_ROWS * P)        // 6240 floats
#define SLOT_B    (STAGEF * 4)        // 24960 bytes
#define RING_B    (3 * SLOT_B)        // 74880 bytes dynamic smem
#define GP        25                  // G row pitch

__device__ float        g_scratch[B_SAMPLES];
__device__ unsigned int g_count = 0;

__device__ __forceinline__ unsigned int smem_u32(const void* p) {
    unsigned int a;
    asm("{ .reg .u64 t; cvta.to.shared.u64 t, %1; cvt.u32.u64 %0, t; }" : "=r"(a) : "l"(p));
    return a;
}
__device__ __forceinline__ void cp16(unsigned int dst, const float* src) {
    asm volatile("cp.async.cg.shared.global [%0], [%1], 16;" :: "r"(dst), "l"(src));
}
__device__ __forceinline__ void cp_commit() { asm volatile("cp.async.commit_group;"); }
__device__ __forceinline__ void cp_wait1()  { asm volatile("cp.async.wait_group 1;"); }
__device__ __forceinline__ float lds32(unsigned int a) {
    float v;
    asm volatile("ld.shared.f32 %0, [%1];" : "=f"(v) : "r"(a));
    return v;
}
__device__ __forceinline__ uint32_t f2tf(float f) {
    uint32_t u;
    asm("cvt.rna.tf32.f32 %0, %1;" : "=r"(u) : "f"(f));
    return u;
}
__device__ __forceinline__ void mma8(float* d, uint32_t a0, uint32_t a1,
                                     uint32_t a2, uint32_t a3,
                                     uint32_t b0, uint32_t b1) {
    asm volatile(
        "mma.sync.aligned.m16n8k8.row.col.f32.tf32.tf32.f32 "
        "{%0,%1,%2,%3}, {%4,%5,%6,%7}, {%8,%9}, {%0,%1,%2,%3};"
        : "+f"(d[0]), "+f"(d[1]), "+f"(d[2]), "+f"(d[3])
        : "r"(a0), "r"(a1), "r"(a2), "r"(a3), "r"(b0), "r"(b1));
}

__global__ __launch_bounds__(THREADS)
void gram_mma_kernel(const float* __restrict__ feat, float* __restrict__ out) {
    extern __shared__ float ring[];            // 3 slots of [24][P]
    __shared__ float sinv[M_ROWS];
    __shared__ float marr[M_ROWS];
    __shared__ float sred[THREADS];
    __shared__ int   s_last;

    const int tid  = threadIdx.x;
    const int ws   = tid >> 5;            // warp = split-K slice in each stage
    const int lane = tid & 31;
    const int gid  = lane >> 2;           // fragment row in group (0..7)
    const int q    = lane & 3;            // fragment quad col (0..3)
    const int b    = blockIdx.x;
    const float* base = feat + (size_t)b * (M_ROWS * D_DIM);
    const unsigned int rb0 = smem_u32(ring);

    float acc00[4] = {0,0,0,0}, acc01[4] = {0,0,0,0};
    float acc02[4] = {0,0,0,0}, acc11[4] = {0,0,0,0};

    // lane-invariant byte offsets within a slot (rows gid, gid+8, gid+16)
    const unsigned int o0 = 4u * (unsigned)(gid * P + q);
    const unsigned int o1 = o0 + 4u * (unsigned)(8 * P);
    const unsigned int o2 = o0 + 4u * (unsigned)(16 * P);

    // ---- staging: 1536 float4 per stage over 128 threads (12 each) ----
    auto issue_stage = [&](int st) {
        const unsigned int slot = rb0 + (unsigned)((st % 3) * SLOT_B);
        const float* src = base + st * CHUNK;
#pragma unroll
        for (int i = 0; i < 12; i++) {
            int e = tid + i * THREADS;            // 0..1535
            int r = e >> 6, c = e & 63;           // row, float4 col
            cp16(slot + 4u * (unsigned)(r * P + c * 4),
                 src + (size_t)r * D_DIM + c * 4);
        }
    };

    issue_stage(0); cp_commit();
    issue_stage(1); cp_commit();

    // ---- main loop: depth-2 prefetch, 1 barrier/stage (R10 structure) ----
    for (int s = 0; s < NSTAGE; ++s) {
        cp_wait1();
        __syncthreads();                 // stage s visible; slot (s+2)%3 free
        if (s + 2 < NSTAGE) issue_stage(s + 2);
        cp_commit();                     // empty commit keeps group accounting

        const unsigned int slot = rb0 + (unsigned)((s % 3) * SLOT_B);
#pragma unroll
        for (int j = 0; j < 8; ++j) {
            const unsigned int ko = 4u * (unsigned)((ws + 4 * j) * 8);  // bytes
            uint32_t a0 = f2tf(lds32(slot + o0 + ko));
            uint32_t a2 = f2tf(lds32(slot + o0 + ko + 16u));
            uint32_t a1 = f2tf(lds32(slot + o1 + ko));
            uint32_t a3 = f2tf(lds32(slot + o1 + ko + 16u));
            uint32_t t0 = f2tf(lds32(slot + o2 + ko));
            uint32_t t2 = f2tf(lds32(slot + o2 + ko + 16u));
            mma8(acc00, a0, a1, a2, a3, a0, a2);   // G[0:16,  0:8 ]
            mma8(acc01, a0, a1, a2, a3, a1, a3);   // G[0:16,  8:16]
            mma8(acc02, a0, a1, a2, a3, t0, t2);   // G[0:16, 16:24]
            mma8(acc11, t0, 0u, t2, 0u, t0, t2);   // G[16:24,16:24]
        }
    }
    __syncthreads();   // all warps done with ring before overlay

    // ---- per-warp partials -> overlay on ring (4 x 600 floats) ----
    {
        float* gp = ring + ws * (M_ROWS * GP);
        gp[gid * GP + 2*q]             = acc00[0];
        gp[gid * GP + 2*q + 1]         = acc00[1];
        gp[(gid+8) * GP + 2*q]         = acc00[2];
        gp[(gid+8) * GP + 2*q + 1]     = acc00[3];
        gp[gid * GP + 8 + 2*q]         = acc01[0];
        gp[gid * GP + 8 + 2*q + 1]     = acc01[1];
        gp[(gid+8) * GP + 8 + 2*q]     = acc01[2];
        gp[(gid+8) * GP + 8 + 2*q + 1] = acc01[3];
        gp[gid * GP + 16 + 2*q]        = acc02[0];
        gp[gid * GP + 16 + 2*q + 1]    = acc02[1];
        gp[(gid+8) * GP + 16 + 2*q]    = acc02[2];
        gp[(gid+8) * GP + 16 + 2*q+1]  = acc02[3];
        gp[(16+gid) * GP + 16 + 2*q]   = acc11[0];
        gp[(16+gid) * GP + 16 + 2*q+1] = acc11[1];
    }
    __syncthreads();

    // ---- sum 4 split-K partials (448 valid entries) ----
    for (int e = tid; e < 448; e += THREADS) {
        int r, c;
        if (e < 384) { r = e / 24; c = e % 24; }
        else { int f = e - 384; r = 16 + f / 8; c = 16 + f % 8; }
        float v = 0.f;
#pragma unroll
        for (int w = 0; w < 4; w++) v += ring[w * (M_ROWS * GP) + r * GP + c];
        ring[r * GP + c] = v;
    }
    __syncthreads();

    // ---- norms ----
    if (tid < M_ROWS) {
        float nr = sqrtf(ring[tid * GP + tid]);
        sinv[tid] = 1.0f / fmaxf(nr, 1e-12f);
    }
    __syncthreads();

    // ---- per-anchor masked log-softmax (reference: no max subtraction) ----
    if (tid < M_ROWS) {
        const int m = tid;
        const float im = sinv[m];
        const int cm = m % 12;
        float denom = 0.f, possum = 0.f, cnt = 0.f;
#pragma unroll
        for (int n = 0; n < M_ROWS; ++n) {
            if (n == m) continue;
            float gv = (m < 16 || n >= 16) ? ring[m * GP + n] : ring[n * GP + m];
            float logit = gv * im * sinv[n] * 10.0f;   // /T, T=0.1
            denom += expf(logit);
            int dc = cm - (n % 12); if (dc < 0) dc = -dc;
            if (dc <= 1) { possum += logit; cnt += 1.f; }
        }
        marr[m] = (possum - cnt * logf(denom)) / (cnt + 1e-6f);
    }
    __syncthreads();
    if (tid == 0) {
        float s = 0.f;
#pragma unroll
        for (int n = 0; n < M_ROWS; n++) s += marr[n];
        g_scratch[b] = s * (-0.1f / 24.0f);
    }

    // ---- fused deterministic final reduction (last CTA) ----
    if (tid == 0) {
        __threadfence();
        unsigned int old = atomicAdd(&g_count, 1u);
        s_last = (old == GRID - 1) ? 1 : 0;
    }
    __syncthreads();
    if (s_last) {
        __threadfence();
        sred[tid] = g_scratch[tid] + g_scratch[tid + 128]
                  + g_scratch[tid + 256] + g_scratch[tid + 384];
        __syncthreads();
#pragma unroll
        for (int w = 64; w > 0; w >>= 1) {
            if (tid < w) sred[tid] += sred[tid + w];
            __syncthreads();
        }
        if (tid == 0) {
            out[0] = sred[0] * (1.0f / (float)B_SAMPLES);
            g_count = 0;   // reset for next graph replay
        }
    }
}

extern "C" void kernel_launch(void* const* d_in, const int* in_sizes, int n_in,
                              void* d_out, int out_size) {
    const float* feat = (const float*)d_in[2];
    static int configured = 0;
    if (!configured) {
        cudaFuncSetAttribute(gram_mma_kernel,
                             cudaFuncAttributeMaxDynamicSharedMemorySize, RING_B);
        configured = 1;
    }
    gram_mma_kernel<<<GRID, THREADS, RING_B>>>(feat, (float*)d_out);
}

// round 16
// speedup vs baseline: 1.2502x; 1.2502x over previous
#include <cuda_runtime.h>
#include <math.h>
#include <stdint.h>

#define B_SAMPLES 512
#define M_ROWS    24
#define D_DIM     4096
#define CHUNK     256                 // floats of K per stage (1KB per row)
#define NSTAGE    (D_DIM / CHUNK)     // 16
#define THREADS   128                 // 4 warps
#define GRID      B_SAMPLES
#define P         260                 // smem row pitch (floats): 260%32==4 bank-spread
#define STAGEF    (M_ROWS * P)        // 6240 floats
#define SLOT_B    (STAGEF * 4)        // 24960 bytes
#define DEPTH     2
#define RING_B    (DEPTH * SLOT_B)    // 49920 bytes dynamic smem -> 4 CTAs/SM
#define GP        25                  // G row pitch

__device__ float        g_scratch[B_SAMPLES];
__device__ unsigned int g_count = 0;

__device__ __forceinline__ unsigned int smem_u32(const void* p) {
    unsigned int a;
    asm("{ .reg .u64 t; cvta.to.shared.u64 t, %1; cvt.u32.u64 %0, t; }" : "=r"(a) : "l"(p));
    return a;
}
__device__ __forceinline__ void cp16(unsigned int dst, const float* src) {
    asm volatile("cp.async.cg.shared.global [%0], [%1], 16;" :: "r"(dst), "l"(src));
}
__device__ __forceinline__ void cp_commit() { asm volatile("cp.async.commit_group;"); }
__device__ __forceinline__ void cp_wait1()  { asm volatile("cp.async.wait_group 1;"); }
__device__ __forceinline__ float lds32(unsigned int a) {
    float v;
    asm volatile("ld.shared.f32 %0, [%1];" : "=f"(v) : "r"(a));
    return v;
}
__device__ __forceinline__ uint32_t f2tf(float f) {
    uint32_t u;
    asm("cvt.rna.tf32.f32 %0, %1;" : "=r"(u) : "f"(f));
    return u;
}
__device__ __forceinline__ void mma8(float* d, uint32_t a0, uint32_t a1,
                                     uint32_t a2, uint32_t a3,
                                     uint32_t b0, uint32_t b1) {
    asm volatile(
        "mma.sync.aligned.m16n8k8.row.col.f32.tf32.tf32.f32 "
        "{%0,%1,%2,%3}, {%4,%5,%6,%7}, {%8,%9}, {%0,%1,%2,%3};"
        : "+f"(d[0]), "+f"(d[1]), "+f"(d[2]), "+f"(d[3])
        : "r"(a0), "r"(a1), "r"(a2), "r"(a3), "r"(b0), "r"(b1));
}

__global__ __launch_bounds__(THREADS)
void gram_mma_kernel(const float* __restrict__ feat, float* __restrict__ out) {
    extern __shared__ float ring[];            // 2 slots of [24][P]
    __shared__ float sinv[M_ROWS];
    __shared__ float marr[M_ROWS];
    __shared__ float sred[THREADS];
    __shared__ int   s_last;

    const int tid  = threadIdx.x;
    const int ws   = tid >> 5;            // warp = split-K slice in each stage
    const int lane = tid & 31;
    const int gid  = lane >> 2;           // fragment row in group (0..7)
    const int q    = lane & 3;            // fragment quad col (0..3)
    const int b    = blockIdx.x;
    const float* base = feat + (size_t)b * (M_ROWS * D_DIM);
    const unsigned int rb0 = smem_u32(ring);

    float acc00[4] = {0,0,0,0}, acc01[4] = {0,0,0,0};
    float acc02[4] = {0,0,0,0}, acc11[4] = {0,0,0,0};

    // lane-invariant byte offsets within a slot (rows gid, gid+8, gid+16)
    const unsigned int o0 = 4u * (unsigned)(gid * P + q);
    const unsigned int o1 = o0 + 4u * (unsigned)(8 * P);
    const unsigned int o2 = o0 + 4u * (unsigned)(16 * P);

    // ---- staging: 1536 float4 per stage over 128 threads (12 each) ----
    auto issue_stage = [&](int st) {
        const unsigned int slot = rb0 + (unsigned)((st & 1) * SLOT_B);
        const float* src = base + st * CHUNK;
#pragma unroll
        for (int i = 0; i < 12; i++) {
            int e = tid + i * THREADS;            // 0..1535
            int r = e >> 6, c = e & 63;           // row, float4 col
            cp16(slot + 4u * (unsigned)(r * P + c * 4),
                 src + (size_t)r * D_DIM + c * 4);
        }
    };

    issue_stage(0); cp_commit();
    issue_stage(1); cp_commit();

    // ---- main loop: double buffer, 2 barriers/stage (16 stages) ----
    for (int s = 0; s < NSTAGE; ++s) {
        cp_wait1();                      // stage s's group retired
        __syncthreads();                 // stage s visible to all warps

        const unsigned int slot = rb0 + (unsigned)((s & 1) * SLOT_B);
#pragma unroll
        for (int j = 0; j < 8; ++j) {
            const unsigned int ko = 4u * (unsigned)((ws + 4 * j) * 8);  // bytes
            uint32_t a0 = f2tf(lds32(slot + o0 + ko));
            uint32_t a2 = f2tf(lds32(slot + o0 + ko + 16u));
            uint32_t a1 = f2tf(lds32(slot + o1 + ko));
            uint32_t a3 = f2tf(lds32(slot + o1 + ko + 16u));
            uint32_t t0 = f2tf(lds32(slot + o2 + ko));
            uint32_t t2 = f2tf(lds32(slot + o2 + ko + 16u));
            mma8(acc00, a0, a1, a2, a3, a0, a2);   // G[0:16,  0:8 ]
            mma8(acc01, a0, a1, a2, a3, a1, a3);   // G[0:16,  8:16]
            mma8(acc02, a0, a1, a2, a3, t0, t2);   // G[0:16, 16:24]
            mma8(acc11, t0, 0u, t2, 0u, t0, t2);   // G[16:24,16:24]
        }
        __syncthreads();                 // all warps done reading slot s&1
        if (s + 2 < NSTAGE) issue_stage(s + 2);
        cp_commit();                     // empty commit keeps group accounting
    }

    // ---- per-warp partials -> overlay on ring (4 x 600 floats) ----
    {
        float* gp = ring + ws * (M_ROWS * GP);
        gp[gid * GP + 2*q]             = acc00[0];
        gp[gid * GP + 2*q + 1]         = acc00[1];
        gp[(gid+8) * GP + 2*q]         = acc00[2];
        gp[(gid+8) * GP + 2*q + 1]     = acc00[3];
        gp[gid * GP + 8 + 2*q]         = acc01[0];
        gp[gid * GP + 8 + 2*q + 1]     = acc01[1];
        gp[(gid+8) * GP + 8 + 2*q]     = acc01[2];
        gp[(gid+8) * GP + 8 + 2*q + 1] = acc01[3];
        gp[gid * GP + 16 + 2*q]        = acc02[0];
        gp[gid * GP + 16 + 2*q + 1]    = acc02[1];
        gp[(gid+8) * GP + 16 + 2*q]    = acc02[2];
        gp[(gid+8) * GP + 16 + 2*q+1]  = acc02[3];
        gp[(16+gid) * GP + 16 + 2*q]   = acc11[0];
        gp[(16+gid) * GP + 16 + 2*q+1] = acc11[1];
    }
    __syncthreads();

    // ---- sum 4 split-K partials (448 valid entries) ----
    for (int e = tid; e < 448; e += THREADS) {
        int r, c;
        if (e < 384) { r = e / 24; c = e % 24; }
        else { int f = e - 384; r = 16 + f / 8; c = 16 + f % 8; }
        float v = 0.f;
#pragma unroll
        for (int w = 0; w < 4; w++) v += ring[w * (M_ROWS * GP) + r * GP + c];
        ring[r * GP + c] = v;
    }
    __syncthreads();

    // ---- norms ----
    if (tid < M_ROWS) {
        float nr = sqrtf(ring[tid * GP + tid]);
        sinv[tid] = 1.0f / fmaxf(nr, 1e-12f);
    }
    __syncthreads();

    // ---- per-anchor masked log-softmax (reference: no max subtraction) ----
    if (tid < M_ROWS) {
        const int m = tid;
        const float im = sinv[m];
        const int cm = m % 12;
        float denom = 0.f, possum = 0.f, cnt = 0.f;
#pragma unroll
        for (int n = 0; n < M_ROWS; ++n) {
            if (n == m) continue;
            float gv = (m < 16 || n >= 16) ? ring[m * GP + n] : ring[n * GP + m];
            float logit = gv * im * sinv[n] * 10.0f;   // /T, T=0.1
            denom += expf(logit);
            int dc = cm - (n % 12); if (dc < 0) dc = -dc;
            if (dc <= 1) { possum += logit; cnt += 1.f; }
        }
        marr[m] = (possum - cnt * logf(denom)) / (cnt + 1e-6f);
    }
    __syncthreads();
    if (tid == 0) {
        float s = 0.f;
#pragma unroll
        for (int n = 0; n < M_ROWS; n++) s += marr[n];
        g_scratch[b] = s * (-0.1f / 24.0f);
    }

    // ---- fused deterministic final reduction (last CTA) ----
    if (tid == 0) {
        __threadfence();
        unsigned int old = atomicAdd(&g_count, 1u);
        s_last = (old == GRID - 1) ? 1 : 0;
    }
    __syncthreads();
    if (s_last) {
        __threadfence();
        sred[tid] = g_scratch[tid] + g_scratch[tid + 128]
                  + g_scratch[tid + 256] + g_scratch[tid + 384];
        __syncthreads();
#pragma unroll
        for (int w = 64; w > 0; w >>= 1) {
            if (tid < w) sred[tid] += sred[tid + w];
            __syncthreads();
        }
        if (tid == 0) {
            out[0] = sred[0] * (1.0f / (float)B_SAMPLES);
            g_count = 0;   // reset for next graph replay
        }
    }
}

extern "C" void kernel_launch(void* const* d_in, const int* in_sizes, int n_in,
                              void* d_out, int out_size) {
    const float* feat = (const float*)d_in[2];
    static int configured = 0;
    if (!configured) {
        cudaFuncSetAttribute(gram_mma_kernel,
                             cudaFuncAttributeMaxDynamicSharedMemorySize, RING_B);
        configured = 1;
    }
    gram_mma_kernel<<<GRID, THREADS, RING_B>>>(feat, (float*)d_out);
}

// round 17
// speedup vs baseline: 1.2935x; 1.0347x over previous
#include <cuda_runtime.h>
#include <math.h>
#include <stdint.h>

#define B_SAMPLES 512
#define M_ROWS    24
#define D_DIM     4096
#define CHUNK     128                 // floats of K per stage
#define NSTAGE    (D_DIM / CHUNK)     // 32
#define THREADS   128                 // 4 warps
#define GRID      B_SAMPLES
#define P         132                 // smem row pitch (floats): bank-spread
#define STAGEF    (M_ROWS * P)        // 3168 floats
#define SLOT_B    (STAGEF * 4)        // 12672 bytes
#define RING_B    (3 * SLOT_B)        // 38016 bytes dynamic smem
#define GP        25                  // G row pitch

__device__ float        g_scratch[B_SAMPLES];
__device__ unsigned int g_count = 0;

__device__ __forceinline__ unsigned int smem_u32(const void* p) {
    unsigned int a;
    asm("{ .reg .u64 t; cvta.to.shared.u64 t, %1; cvt.u32.u64 %0, t; }" : "=r"(a) : "l"(p));
    return a;
}
__device__ __forceinline__ void cp16(unsigned int dst, const float* src) {
    asm volatile("cp.async.cg.shared.global [%0], [%1], 16;" :: "r"(dst), "l"(src));
}
__device__ __forceinline__ void cp_commit() { asm volatile("cp.async.commit_group;"); }
__device__ __forceinline__ void cp_wait1()  { asm volatile("cp.async.wait_group 1;"); }
__device__ __forceinline__ void l2_prefetch(const float* p) {
    asm volatile("prefetch.global.L2 [%0];" :: "l"(p));
}
__device__ __forceinline__ float lds32(unsigned int a) {
    float v;
    asm volatile("ld.shared.f32 %0, [%1];" : "=f"(v) : "r"(a));
    return v;
}
__device__ __forceinline__ uint32_t f2tf(float f) {
    uint32_t u;
    asm("cvt.rna.tf32.f32 %0, %1;" : "=r"(u) : "f"(f));
    return u;
}
__device__ __forceinline__ void mma8(float* d, uint32_t a0, uint32_t a1,
                                     uint32_t a2, uint32_t a3,
                                     uint32_t b0, uint32_t b1) {
    asm volatile(
        "mma.sync.aligned.m16n8k8.row.col.f32.tf32.tf32.f32 "
        "{%0,%1,%2,%3}, {%4,%5,%6,%7}, {%8,%9}, {%0,%1,%2,%3};"
        : "+f"(d[0]), "+f"(d[1]), "+f"(d[2]), "+f"(d[3])
        : "r"(a0), "r"(a1), "r"(a2), "r"(a3), "r"(b0), "r"(b1));
}

__global__ __launch_bounds__(THREADS)
void gram_mma_kernel(const float* __restrict__ feat, float* __restrict__ out) {
    extern __shared__ float ring[];            // 3 slots of [24][P]
    __shared__ float sinv[M_ROWS];
    __shared__ float marr[M_ROWS];
    __shared__ float sred[THREADS];
    __shared__ int   s_last;

    const int tid  = threadIdx.x;
    const int ws   = tid >> 5;            // warp = split-K slice in each stage
    const int lane = tid & 31;
    const int gid  = lane >> 2;           // fragment row in group (0..7)
    const int q    = lane & 3;            // fragment quad col (0..3)
    const int b    = blockIdx.x;
    const float* base = feat + (size_t)b * (M_ROWS * D_DIM);
    const unsigned int rb0 = smem_u32(ring);

    float acc00[4] = {0,0,0,0}, acc01[4] = {0,0,0,0};
    float acc02[4] = {0,0,0,0}, acc11[4] = {0,0,0,0};

    // lane-invariant byte offsets within a slot (rows gid, gid+8, gid+16)
    const unsigned int o0 = 4u * (unsigned)(gid * P + q);
    const unsigned int o1 = o0 + 4u * (unsigned)(8 * P);
    const unsigned int o2 = o0 + 4u * (unsigned)(16 * P);

    // per-thread L2 prefetch target: row tid>>2 (0..23), 128B line tid&3 (0..3)
    const float* pfb = base + (size_t)(tid >> 2) * D_DIM + (tid & 3) * 32;
    const bool   pfv = (tid < 96);

    // ---- staging: 768 float4 per stage over 128 threads (6 each) ----
    auto issue_stage = [&](int st) {
        const unsigned int slot = rb0 + (unsigned)((st % 3) * SLOT_B);
        const float* src = base + st * CHUNK;
#pragma unroll
        for (int i = 0; i < 6; i++) {
            int e = tid + i * THREADS;            // 0..767
            int r = e >> 5, c = e & 31;           // row, float4 col
            cp16(slot + 4u * (unsigned)(r * P + c * 4),
                 src + (size_t)r * D_DIM + c * 4);
        }
    };

    // L2-warm stages 2,3 before the pipeline catches up to them
    if (pfv) { l2_prefetch(pfb + 2 * CHUNK); l2_prefetch(pfb + 3 * CHUNK); }

    issue_stage(0); cp_commit();
    issue_stage(1); cp_commit();

    // ---- main loop: depth-2 cp.async + distance-4 L2 prefetch ----
    for (int s = 0; s < NSTAGE; ++s) {
        cp_wait1();
        __syncthreads();                 // stage s visible; slot (s+2)%3 free
        if (s + 2 < NSTAGE) issue_stage(s + 2);
        cp_commit();                     // empty commit keeps group accounting
        if (pfv && s + 4 < NSTAGE) l2_prefetch(pfb + (s + 4) * CHUNK);

        const unsigned int slot = rb0 + (unsigned)((s % 3) * SLOT_B);
#pragma unroll
        for (int j = 0; j < 4; ++j) {
            const unsigned int ko = 4u * (unsigned)((ws + 4 * j) * 8);  // bytes
            uint32_t a0 = f2tf(lds32(slot + o0 + ko));
            uint32_t a2 = f2tf(lds32(slot + o0 + ko + 16u));
            uint32_t a1 = f2tf(lds32(slot + o1 + ko));
            uint32_t a3 = f2tf(lds32(slot + o1 + ko + 16u));
            uint32_t t0 = f2tf(lds32(slot + o2 + ko));
            uint32_t t2 = f2tf(lds32(slot + o2 + ko + 16u));
            mma8(acc00, a0, a1, a2, a3, a0, a2);   // G[0:16,  0:8 ]
            mma8(acc01, a0, a1, a2, a3, a1, a3);   // G[0:16,  8:16]
            mma8(acc02, a0, a1, a2, a3, t0, t2);   // G[0:16, 16:24]
            mma8(acc11, t0, 0u, t2, 0u, t0, t2);   // G[16:24,16:24]
        }
    }
    __syncthreads();   // all warps done with ring before overlay

    // ---- per-warp partials -> overlay on ring (4 x 600 floats) ----
    {
        float* gp = ring + ws * (M_ROWS * GP);
        gp[gid * GP + 2*q]             = acc00[0];
        gp[gid * GP + 2*q + 1]         = acc00[1];
        gp[(gid+8) * GP + 2*q]         = acc00[2];
        gp[(gid+8) * GP + 2*q + 1]     = acc00[3];
        gp[gid * GP + 8 + 2*q]         = acc01[0];
        gp[gid * GP + 8 + 2*q + 1]     = acc01[1];
        gp[(gid+8) * GP + 8 + 2*q]     = acc01[2];
        gp[(gid+8) * GP + 8 + 2*q + 1] = acc01[3];
        gp[gid * GP + 16 + 2*q]        = acc02[0];
        gp[gid * GP + 16 + 2*q + 1]    = acc02[1];
        gp[(gid+8) * GP + 16 + 2*q]    = acc02[2];
        gp[(gid+8) * GP + 16 + 2*q+1]  = acc02[3];
        gp[(16+gid) * GP + 16 + 2*q]   = acc11[0];
        gp[(16+gid) * GP + 16 + 2*q+1] = acc11[1];
    }
    __syncthreads();

    // ---- sum 4 split-K partials (448 valid entries) ----
    for (int e = tid; e < 448; e += THREADS) {
        int r, c;
        if (e < 384) { r = e / 24; c = e % 24; }
        else { int f = e - 384; r = 16 + f / 8; c = 16 + f % 8; }
        float v = 0.f;
#pragma unroll
        for (int w = 0; w < 4; w++) v += ring[w * (M_ROWS * GP) + r * GP + c];
        ring[r * GP + c] = v;
    }
    __syncthreads();

    // ---- norms ----
    if (tid < M_ROWS) {
        float nr = sqrtf(ring[tid * GP + tid]);
        sinv[tid] = 1.0f / fmaxf(nr, 1e-12f);
    }
    __syncthreads();

    // ---- per-anchor masked log-softmax (reference: no max subtraction) ----
    if (tid < M_ROWS) {
        const int m = tid;
        const float im = sinv[m];
        const int cm = m % 12;
        float denom = 0.f, possum = 0.f, cnt = 0.f;
#pragma unroll
        for (int n = 0; n < M_ROWS; ++n) {
            if (n == m) continue;
            float gv = (m < 16 || n >= 16) ? ring[m * GP + n] : ring[n * GP + m];
            float logit = gv * im * sinv[n] * 10.0f;   // /T, T=0.1
            denom += expf(logit);
            int dc = cm - (n % 12); if (dc < 0) dc = -dc;
            if (dc <= 1) { possum += logit; cnt += 1.f; }
        }
        marr[m] = (possum - cnt * logf(denom)) / (cnt + 1e-6f);
    }
    __syncthreads();
    if (tid == 0) {
        float s = 0.f;
#pragma unroll
        for (int n = 0; n < M_ROWS; n++) s += marr[n];
        g_scratch[b] = s * (-0.1f / 24.0f);
    }

    // ---- fused deterministic final reduction (last CTA) ----
    if (tid == 0) {
        __threadfence();
        unsigned int old = atomicAdd(&g_count, 1u);
        s_last = (old == GRID - 1) ? 1 : 0;
    }
    __syncthreads();
    if (s_last) {
        __threadfence();
        sred[tid] = g_scratch[tid] + g_scratch[tid + 128]
                  + g_scratch[tid + 256] + g_scratch[tid + 384];
        __syncthreads();
#pragma unroll
        for (int w = 64; w > 0; w >>= 1) {
            if (tid < w) sred[tid] += sred[tid + w];
            __syncthreads();
        }
        if (tid == 0) {
            out[0] = sred[0] * (1.0f / (float)B_SAMPLES);
            g_count = 0;   // reset for next graph replay
        }
    }
}

extern "C" void kernel_launch(void* const* d_in, const int* in_sizes, int n_in,
                              void* d_out, int out_size) {
    const float* feat = (const float*)d_in[2];
    static int configured = 0;
    if (!configured) {
        cudaFuncSetAttribute(gram_mma_kernel,
                             cudaFuncAttributeMaxDynamicSharedMemorySize, RING_B);
        configured = 1;
    }
    gram_mma_kernel<<<GRID, THREADS, RING_B>>>(feat, (float*)d_out);
}